// round 7
// baseline (speedup 1.0000x reference)
#include <cuda_runtime.h>
#include <cuda_fp16.h>
#include <cstdint>

// Problem dims
#define T_DIM 8192
#define K_DIM 4096
#define O_DIM 11008
#define QB    64

// Two-term split: A row = [xh(4096) | xl(4096)], B row = [wh(4096) | wl(4096)]
#define AK 8192

// GEMM tiling (R3-proven schedule: 3 stages, cp_wait<1>)
#define BM 128
#define BN 256
#define BK 64                       // 64 fp16 = 128 B per row = one SW128 atom row
#define NSTAGE 3
#define NTHREADS 512
#define KBLK_MAIN 64                // xh*wh
#define KBLK_CORR 128               // xl*wh (kb<64) ++ xh*wl (kb>=64)

#define A_ST_BYTES (BM * 128)       // 16384
#define B_ST_BYTES (BN * 128)       // 32768
#define STAGE_BYTES (A_ST_BYTES + B_ST_BYTES)  // 49152
#define SMEM_TOTAL (NSTAGE * STAGE_BYTES)       // 147456

// fp16 scratch (static device arrays: allocation-free contract)
__device__ __align__(16) __half g_a[(size_t)T_DIM * AK];   // [xh | xl]
__device__ __align__(16) __half g_b[(size_t)O_DIM * AK];   // [wh | wl]

// ---------------------------------------------------------------- helpers
__device__ __forceinline__ uint32_t smem_u32(const void* p) {
    uint32_t a;
    asm("{ .reg .u64 t; cvta.to.shared.u64 t, %1; cvt.u32.u64 %0, t; }" : "=r"(a) : "l"(p));
    return a;
}
__device__ __forceinline__ uint32_t swz(uint32_t off) { return off ^ ((off >> 3) & 0x70); }

__device__ __forceinline__ void cp_async16(uint32_t dst, const void* src) {
    asm volatile("cp.async.cg.shared.global [%0], [%1], 16;\n" :: "r"(dst), "l"(src));
}
__device__ __forceinline__ void cp_commit() { asm volatile("cp.async.commit_group;\n" ::: "memory"); }
template <int N>
__device__ __forceinline__ void cp_wait() { asm volatile("cp.async.wait_group %0;\n" :: "n"(N) : "memory"); }

#define LDSM_X4(r, addr) \
    asm volatile("ldmatrix.sync.aligned.m8n8.x4.shared.b16 {%0,%1,%2,%3}, [%4];" \
        : "=r"((r)[0]), "=r"((r)[1]), "=r"((r)[2]), "=r"((r)[3]) : "r"(addr))

#define MMA16816(c, a, b0, b1) \
    asm volatile("mma.sync.aligned.m16n8k16.row.col.f32.f16.f16.f32 " \
        "{%0,%1,%2,%3}, {%4,%5,%6,%7}, {%8,%9}, {%0,%1,%2,%3};" \
        : "+f"((c)[0]), "+f"((c)[1]), "+f"((c)[2]), "+f"((c)[3]) \
        : "r"((a)[0]), "r"((a)[1]), "r"((a)[2]), "r"((a)[3]), "r"(b0), "r"(b1))

// fp16-accumulate HMMA (2x rate on legacy mma paths); C = 2 regs x 2 halves
#define MMA16816H(c, a, b0, b1) \
    asm volatile("mma.sync.aligned.m16n8k16.row.col.f16.f16.f16.f16 " \
        "{%0,%1}, {%2,%3,%4,%5}, {%6,%7}, {%0,%1};" \
        : "+r"((c)[0]), "+r"((c)[1]) \
        : "r"((a)[0]), "r"((a)[1]), "r"((a)[2]), "r"((a)[3]), "r"(b0), "r"(b1))

// ---------------------------------------------------------------- prep kernels
__global__ void __launch_bounds__(256) xsplit_kernel(const float* __restrict__ x) {
    const size_t n4 = (size_t)T_DIM * K_DIM / 4;
    for (size_t v = (size_t)blockIdx.x * blockDim.x + threadIdx.x; v < n4;
         v += (size_t)gridDim.x * blockDim.x) {
        size_t e = v * 4;
        size_t t = e >> 12;
        size_t i = e & 4095;
        float4 f = reinterpret_cast<const float4*>(x)[v];
        __half h0 = __float2half_rn(f.x), h1 = __float2half_rn(f.y);
        __half h2 = __float2half_rn(f.z), h3 = __float2half_rn(f.w);
        __half l0 = __float2half_rn(f.x - __half2float(h0));
        __half l1 = __float2half_rn(f.y - __half2float(h1));
        __half l2 = __float2half_rn(f.z - __half2float(h2));
        __half l3 = __float2half_rn(f.w - __half2float(h3));
        __half2 hi0 = __halves2half2(h0, h1), hi1 = __halves2half2(h2, h3);
        __half2 lo0 = __halves2half2(l0, l1), lo1 = __halves2half2(l2, l3);
        uint2 uh, ul;
        uh.x = *reinterpret_cast<uint32_t*>(&hi0); uh.y = *reinterpret_cast<uint32_t*>(&hi1);
        ul.x = *reinterpret_cast<uint32_t*>(&lo0); ul.y = *reinterpret_cast<uint32_t*>(&lo1);
        *reinterpret_cast<uint2*>(g_a + t * AK + i) = uh;
        *reinterpret_cast<uint2*>(g_a + t * AK + K_DIM + i) = ul;
    }
}

__global__ void __launch_bounds__(256) wsplit_kernel(const float* __restrict__ w,
                                                     const float* __restrict__ s) {
    const size_t n4 = (size_t)O_DIM * K_DIM / 4;
    const int SCOLS = K_DIM / QB;  // 64
    for (size_t v = (size_t)blockIdx.x * blockDim.x + threadIdx.x; v < n4;
         v += (size_t)gridDim.x * blockDim.x) {
        size_t e = v * 4;
        size_t o = e >> 12;
        size_t i = e & 4095;
        float sc = s[(o >> 6) * SCOLS + (i >> 6)];
        float4 f = reinterpret_cast<const float4*>(w)[v];
        float d0 = f.x * sc, d1 = f.y * sc, d2 = f.z * sc, d3 = f.w * sc;
        __half h0 = __float2half_rn(d0), h1 = __float2half_rn(d1);
        __half h2 = __float2half_rn(d2), h3 = __float2half_rn(d3);
        __half l0 = __float2half_rn(d0 - __half2float(h0));
        __half l1 = __float2half_rn(d1 - __half2float(h1));
        __half l2 = __float2half_rn(d2 - __half2float(h2));
        __half l3 = __float2half_rn(d3 - __half2float(h3));
        __half2 hi0 = __halves2half2(h0, h1), hi1 = __halves2half2(h2, h3);
        __half2 lo0 = __halves2half2(l0, l1), lo1 = __halves2half2(l2, l3);
        uint2 uh, ul;
        uh.x = *reinterpret_cast<uint32_t*>(&hi0); uh.y = *reinterpret_cast<uint32_t*>(&hi1);
        ul.x = *reinterpret_cast<uint32_t*>(&lo0); ul.y = *reinterpret_cast<uint32_t*>(&lo1);
        *reinterpret_cast<uint2*>(g_b + o * AK + i) = uh;
        *reinterpret_cast<uint2*>(g_b + o * AK + K_DIM + i) = ul;
    }
}

// ---------------------------------------------------------------- correction GEMM (fp16 acc)
// kb in [0,64):   A block kb^64 = xl,  B block kb = wh
// kb in [64,128): A block kb^64 = xh,  B block kb = wl
// Writes out = xl*wh + xh*wl.
__global__ void __launch_bounds__(NTHREADS, 1) gemm_corr(float* __restrict__ out) {
    extern __shared__ char smem[];
    const uint32_t sbase = smem_u32(smem);
    const int tid = threadIdx.x;
    const int wid = tid >> 5;
    const int lid = tid & 31;

    const int t0 = blockIdx.x * BM;
    const int o0 = blockIdx.y * BN;

    const __half* Ag = g_a + (size_t)t0 * AK;
    const __half* Bg = g_b + (size_t)o0 * AK;

    auto load_stage = [&](int st, int kb) {
        if (kb < KBLK_CORR) {
            const uint32_t abase = sbase + st * STAGE_BYTES;
            const uint32_t bbase = abase + A_ST_BYTES;
            const int ak = (kb ^ 64) * BK;
            const int bk = kb * BK;
            #pragma unroll
            for (int c = tid; c < (BM + BN) * 8; c += NTHREADS) {
                int row = c >> 3, ch = c & 7;
                if (row < BM)
                    cp_async16(abase + swz(row * 128 + ch * 16),
                               Ag + (size_t)row * AK + ak + ch * 8);
                else
                    cp_async16(bbase + swz((row - BM) * 128 + ch * 16),
                               Bg + (size_t)(row - BM) * AK + bk + ch * 8);
            }
        }
        cp_commit();
    };

    const int warp_m = wid & 1;
    const int warp_n = wid >> 1;
    const int m_off = warp_m * 64;
    const int n_off = warp_n * 32;
    const int lrow = lid & 15;
    const int lc16 = lid >> 4;

    uint32_t preA[4], preB[2];
    #pragma unroll
    for (int mi = 0; mi < 4; mi++)
        preA[mi] = swz((uint32_t)((m_off + mi * 16 + lrow) * 128 + lc16 * 16));
    #pragma unroll
    for (int nj = 0; nj < 2; nj++)
        preB[nj] = swz((uint32_t)((n_off + nj * 16 + lrow) * 128 + lc16 * 16));

    uint32_t acc[4][4][2];   // fp16x2 accumulators
    #pragma unroll
    for (int mi = 0; mi < 4; mi++)
        #pragma unroll
        for (int ni = 0; ni < 4; ni++) { acc[mi][ni][0] = 0u; acc[mi][ni][1] = 0u; }

    load_stage(0, 0);
    load_stage(1, 1);

    for (int kb = 0; kb < KBLK_CORR; kb++) {
        cp_wait<1>();
        __syncthreads();
        load_stage((kb + 2) % NSTAGE, kb + 2);

        const uint32_t sA = sbase + (kb % NSTAGE) * STAGE_BYTES;
        const uint32_t sB = sA + A_ST_BYTES;
        #pragma unroll
        for (int ks = 0; ks < 4; ks++) {
            const uint32_t xk = ks * 32;
            uint32_t a[4][4], b[2][4];
            #pragma unroll
            for (int mi = 0; mi < 4; mi++) LDSM_X4(a[mi], sA + (preA[mi] ^ xk));
            #pragma unroll
            for (int nj = 0; nj < 2; nj++) LDSM_X4(b[nj], sB + (preB[nj] ^ xk));
            #pragma unroll
            for (int mi = 0; mi < 4; mi++)
                #pragma unroll
                for (int ni = 0; ni < 4; ni++)
                    MMA16816H(acc[mi][ni], a[mi], b[ni >> 1][ni & 1], b[ni >> 1][2 + (ni & 1)]);
        }
    }

    // Epilogue: convert fp16 pairs -> f32, write out
    #pragma unroll
    for (int mi = 0; mi < 4; mi++) {
        const int r0 = t0 + m_off + mi * 16 + (lid >> 2);
        #pragma unroll
        for (int ni = 0; ni < 4; ni++) {
            const int c = o0 + n_off + ni * 8 + ((lid & 3) << 1);
            __half2 v0 = *reinterpret_cast<__half2*>(&acc[mi][ni][0]);
            __half2 v1 = *reinterpret_cast<__half2*>(&acc[mi][ni][1]);
            *reinterpret_cast<float2*>(out + (size_t)r0 * O_DIM + c) =
                make_float2(__low2float(v0), __high2float(v0));
            *reinterpret_cast<float2*>(out + (size_t)(r0 + 8) * O_DIM + c) =
                make_float2(__low2float(v1), __high2float(v1));
        }
    }
}

// ---------------------------------------------------------------- main GEMM (f32 acc, accumulates)
__global__ void __launch_bounds__(NTHREADS, 1) gemm_main(float* __restrict__ out) {
    extern __shared__ char smem[];
    const uint32_t sbase = smem_u32(smem);
    const int tid = threadIdx.x;
    const int wid = tid >> 5;
    const int lid = tid & 31;

    const int t0 = blockIdx.x * BM;
    const int o0 = blockIdx.y * BN;

    const __half* Ag = g_a + (size_t)t0 * AK;
    const __half* Bg = g_b + (size_t)o0 * AK;

    auto load_stage = [&](int st, int kb) {
        if (kb < KBLK_MAIN) {
            const uint32_t abase = sbase + st * STAGE_BYTES;
            const uint32_t bbase = abase + A_ST_BYTES;
            const int kk = kb * BK;
            #pragma unroll
            for (int c = tid; c < (BM + BN) * 8; c += NTHREADS) {
                int row = c >> 3, ch = c & 7;
                if (row < BM)
                    cp_async16(abase + swz(row * 128 + ch * 16),
                               Ag + (size_t)row * AK + kk + ch * 8);
                else
                    cp_async16(bbase + swz((row - BM) * 128 + ch * 16),
                               Bg + (size_t)(row - BM) * AK + kk + ch * 8);
            }
        }
        cp_commit();
    };

    const int warp_m = wid & 1;
    const int warp_n = wid >> 1;
    const int m_off = warp_m * 64;
    const int n_off = warp_n * 32;
    const int lrow = lid & 15;
    const int lc16 = lid >> 4;

    uint32_t preA[4], preB[2];
    #pragma unroll
    for (int mi = 0; mi < 4; mi++)
        preA[mi] = swz((uint32_t)((m_off + mi * 16 + lrow) * 128 + lc16 * 16));
    #pragma unroll
    for (int nj = 0; nj < 2; nj++)
        preB[nj] = swz((uint32_t)((n_off + nj * 16 + lrow) * 128 + lc16 * 16));

    float acc[4][4][4];
    #pragma unroll
    for (int mi = 0; mi < 4; mi++)
        #pragma unroll
        for (int ni = 0; ni < 4; ni++)
            #pragma unroll
            for (int q = 0; q < 4; q++) acc[mi][ni][q] = 0.f;

    load_stage(0, 0);
    load_stage(1, 1);

    for (int kb = 0; kb < KBLK_MAIN; kb++) {
        cp_wait<1>();
        __syncthreads();
        load_stage((kb + 2) % NSTAGE, kb + 2);

        const uint32_t sA = sbase + (kb % NSTAGE) * STAGE_BYTES;
        const uint32_t sB = sA + A_ST_BYTES;
        #pragma unroll
        for (int ks = 0; ks < 4; ks++) {
            const uint32_t xk = ks * 32;
            uint32_t a[4][4], b[2][4];
            #pragma unroll
            for (int mi = 0; mi < 4; mi++) LDSM_X4(a[mi], sA + (preA[mi] ^ xk));
            #pragma unroll
            for (int nj = 0; nj < 2; nj++) LDSM_X4(b[nj], sB + (preB[nj] ^ xk));
            #pragma unroll
            for (int mi = 0; mi < 4; mi++)
                #pragma unroll
                for (int ni = 0; ni < 4; ni++)
                    MMA16816(acc[mi][ni], a[mi], b[ni >> 1][ni & 1], b[ni >> 1][2 + (ni & 1)]);
        }
    }

    // Epilogue: accumulate onto correction result
    #pragma unroll
    for (int mi = 0; mi < 4; mi++) {
        const int r0 = t0 + m_off + mi * 16 + (lid >> 2);
        #pragma unroll
        for (int ni = 0; ni < 4; ni++) {
            const int c = o0 + n_off + ni * 8 + ((lid & 3) << 1);
            float2* p0 = reinterpret_cast<float2*>(out + (size_t)r0 * O_DIM + c);
            float2* p1 = reinterpret_cast<float2*>(out + (size_t)(r0 + 8) * O_DIM + c);
            float2 v0 = *p0, v1 = *p1;
            v0.x += acc[mi][ni][0]; v0.y += acc[mi][ni][1];
            v1.x += acc[mi][ni][2]; v1.y += acc[mi][ni][3];
            *p0 = v0; *p1 = v1;
        }
    }
}

// ---------------------------------------------------------------- launch
extern "C" void kernel_launch(void* const* d_in, const int* in_sizes, int n_in,
                              void* d_out, int out_size) {
    (void)in_sizes; (void)n_in; (void)out_size;
    const float* x = (const float*)d_in[0];
    const float* w = (const float*)d_in[1];
    const float* s = (const float*)d_in[2];
    float* out = (float*)d_out;

    xsplit_kernel<<<2048, 256>>>(x);
    wsplit_kernel<<<2048, 256>>>(w, s);

    cudaFuncSetAttribute(gemm_corr, cudaFuncAttributeMaxDynamicSharedMemorySize, SMEM_TOTAL);
    cudaFuncSetAttribute(gemm_main, cudaFuncAttributeMaxDynamicSharedMemorySize, SMEM_TOTAL);
    dim3 grid(T_DIM / BM, O_DIM / BN);  // (64, 43), m fastest
    gemm_corr<<<grid, NTHREADS, SMEM_TOTAL>>>(out);   // out  = xl*wh + xh*wl
    gemm_main<<<grid, NTHREADS, SMEM_TOTAL>>>(out);   // out += xh*wh
}

// round 8
// speedup vs baseline: 1.0920x; 1.0920x over previous
#include <cuda_runtime.h>
#include <cuda_fp16.h>
#include <cstdint>

// Problem dims
#define T_DIM 8192
#define K_DIM 4096
#define O_DIM 11008
#define QB    64

// GEMM tiling: 128x256 CTA tile, K64 slab (128B/row), 3-product schedule K=192 blocks
#define BM 128
#define BN 256
#define NSTAGE 3
#define NTHREADS 256
#define KBLKS 192                   // 64 (xh*wh) + 64 (xh*wl) + 64 (xl*wh)

#define A_SLAB 16384                // 128 rows x 128 B  (pre-swizzled in gmem)
#define B_SLAB 32768                // 256 rows x 128 B  (pre-swizzled in gmem)
#define STAGE_BYTES (A_SLAB + B_SLAB)          // 49152
#define SMEM_BARS (NSTAGE * STAGE_BYTES)       // 147456
#define SMEM_TOTAL (SMEM_BARS + 32)            // + 3 mbarriers

// Pre-swizzled slab storage (static device arrays: allocation-free contract)
// A: [mblk(64)][akb(128: xh 0-63 | xl 64-127)][16384 B]
// B: [oblk(43)][bkb(128: wh 0-63 | wl 64-127)][32768 B]
__device__ __align__(16) uint8_t g_a[(size_t)64 * 128 * A_SLAB];   // 128 MB
__device__ __align__(16) uint8_t g_b[(size_t)43 * 128 * B_SLAB];   // 176 MB

// ---------------------------------------------------------------- helpers
__device__ __forceinline__ uint32_t smem_u32(const void* p) {
    uint32_t a;
    asm("{ .reg .u64 t; cvta.to.shared.u64 t, %1; cvt.u32.u64 %0, t; }" : "=r"(a) : "l"(p));
    return a;
}
__device__ __forceinline__ uint32_t swz(uint32_t off) { return off ^ ((off >> 3) & 0x70); }

__device__ __forceinline__ void mbar_init(uint32_t mbar, uint32_t cnt) {
    asm volatile("mbarrier.init.shared.b64 [%0], %1;" :: "r"(mbar), "r"(cnt) : "memory");
}
__device__ __forceinline__ void mbar_expect_tx(uint32_t mbar, uint32_t tx) {
    asm volatile("mbarrier.arrive.expect_tx.shared.b64 _, [%0], %1;" :: "r"(mbar), "r"(tx) : "memory");
}
__device__ __forceinline__ void mbar_wait(uint32_t mbar, uint32_t parity) {
    asm volatile(
        "{\n\t.reg .pred P1;\n\t"
        "WL_%=:\n\t"
        "mbarrier.try_wait.parity.acquire.cta.shared::cta.b64 P1, [%0], %1, 0x989680;\n\t"
        "@P1 bra.uni WD_%=;\n\t"
        "bra.uni WL_%=;\n\t"
        "WD_%=:\n\t}"
        :: "r"(mbar), "r"(parity) : "memory");
}
__device__ __forceinline__ void bulk_g2s(uint32_t dst, const void* src, uint32_t bytes, uint32_t mbar) {
    asm volatile(
        "cp.async.bulk.shared::cta.global.mbarrier::complete_tx::bytes [%0], [%1], %2, [%3];"
        :: "r"(dst), "l"(src), "r"(bytes), "r"(mbar) : "memory");
}

#define LDSM_X4(r, addr) \
    asm volatile("ldmatrix.sync.aligned.m8n8.x4.shared.b16 {%0,%1,%2,%3}, [%4];" \
        : "=r"((r)[0]), "=r"((r)[1]), "=r"((r)[2]), "=r"((r)[3]) : "r"(addr))

#define MMA16816(c, a, b0, b1) \
    asm volatile("mma.sync.aligned.m16n8k16.row.col.f32.f16.f16.f32 " \
        "{%0,%1,%2,%3}, {%4,%5,%6,%7}, {%8,%9}, {%0,%1,%2,%3};" \
        : "+f"((c)[0]), "+f"((c)[1]), "+f"((c)[2]), "+f"((c)[3]) \
        : "r"((a)[0]), "r"((a)[1]), "r"((a)[2]), "r"((a)[3]), "r"(b0), "r"(b1))

// ---------------------------------------------------------------- prep kernels
// Each thread handles one 16B output chunk (8 halfs) per slab pair.
__global__ void __launch_bounds__(256) xsplit_kernel(const float* __restrict__ x) {
    const size_t nch = (size_t)T_DIM * K_DIM / 8;
    for (size_t v = (size_t)blockIdx.x * blockDim.x + threadIdx.x; v < nch;
         v += (size_t)gridDim.x * blockDim.x) {
        size_t e = v * 8;
        size_t t = e >> 12;          // row (token)
        size_t i = e & 4095;         // col within K
        float4 f0 = reinterpret_cast<const float4*>(x)[v * 2];
        float4 f1 = reinterpret_cast<const float4*>(x)[v * 2 + 1];
        float fs[8] = {f0.x, f0.y, f0.z, f0.w, f1.x, f1.y, f1.z, f1.w};
        uint32_t hw[4], lw[4];
        #pragma unroll
        for (int j = 0; j < 4; j++) {
            __half a0 = __float2half_rn(fs[2 * j]), a1 = __float2half_rn(fs[2 * j + 1]);
            __half b0 = __float2half_rn(fs[2 * j] - __half2float(a0));
            __half b1 = __float2half_rn(fs[2 * j + 1] - __half2float(a1));
            __half2 hh = __halves2half2(a0, a1), ll = __halves2half2(b0, b1);
            hw[j] = *reinterpret_cast<uint32_t*>(&hh);
            lw[j] = *reinterpret_cast<uint32_t*>(&ll);
        }
        size_t slab = ((t >> 7) * 128 + (i >> 6)) * (size_t)A_SLAB;   // xh slab
        uint32_t off = swz((uint32_t)((t & 127) * 128 + ((i & 63) >> 3) * 16));
        *reinterpret_cast<uint4*>(g_a + slab + off) = make_uint4(hw[0], hw[1], hw[2], hw[3]);
        *reinterpret_cast<uint4*>(g_a + slab + (size_t)64 * A_SLAB + off) =
            make_uint4(lw[0], lw[1], lw[2], lw[3]);                   // xl slab (+64)
    }
}

__global__ void __launch_bounds__(256) wsplit_kernel(const float* __restrict__ w,
                                                     const float* __restrict__ s) {
    const size_t nch = (size_t)O_DIM * K_DIM / 8;
    const int SCOLS = K_DIM / QB;  // 64
    for (size_t v = (size_t)blockIdx.x * blockDim.x + threadIdx.x; v < nch;
         v += (size_t)gridDim.x * blockDim.x) {
        size_t e = v * 8;
        size_t o = e >> 12;
        size_t i = e & 4095;
        float sc = s[(o >> 6) * SCOLS + (i >> 6)];
        float4 f0 = reinterpret_cast<const float4*>(w)[v * 2];
        float4 f1 = reinterpret_cast<const float4*>(w)[v * 2 + 1];
        float fs[8] = {f0.x * sc, f0.y * sc, f0.z * sc, f0.w * sc,
                       f1.x * sc, f1.y * sc, f1.z * sc, f1.w * sc};
        uint32_t hw[4], lw[4];
        #pragma unroll
        for (int j = 0; j < 4; j++) {
            __half a0 = __float2half_rn(fs[2 * j]), a1 = __float2half_rn(fs[2 * j + 1]);
            __half b0 = __float2half_rn(fs[2 * j] - __half2float(a0));
            __half b1 = __float2half_rn(fs[2 * j + 1] - __half2float(a1));
            __half2 hh = __halves2half2(a0, a1), ll = __halves2half2(b0, b1);
            hw[j] = *reinterpret_cast<uint32_t*>(&hh);
            lw[j] = *reinterpret_cast<uint32_t*>(&ll);
        }
        size_t slab = ((o >> 8) * 128 + (i >> 6)) * (size_t)B_SLAB;   // wh slab
        uint32_t off = swz((uint32_t)((o & 255) * 128 + ((i & 63) >> 3) * 16));
        *reinterpret_cast<uint4*>(g_b + slab + off) = make_uint4(hw[0], hw[1], hw[2], hw[3]);
        *reinterpret_cast<uint4*>(g_b + slab + (size_t)64 * B_SLAB + off) =
            make_uint4(lw[0], lw[1], lw[2], lw[3]);                   // wl slab (+64)
    }
}

// Per-stage K-block remap (3-product schedule):
//   kb in [0,64):    A slab kb      (xh) * B slab kb      (wh)
//   kb in [64,128):  A slab kb-64   (xh) * B slab kb      (wl)
//   kb in [128,192): A slab kb-64   (xl) * B slab kb-128  (wh)
__device__ __forceinline__ int a_kblk(int kb) { return (kb < 128) ? (kb & 63) : (kb - 64); }
__device__ __forceinline__ int b_kblk(int kb) { return (kb < 128) ? kb : (kb - 128); }

// ---------------------------------------------------------------- GEMM
// 8 warps (256 thr) in 2(m) x 4(n); warp tile 64x64; f32-accumulate HMMA.
__global__ void __launch_bounds__(NTHREADS, 1) gemm_kernel(float* __restrict__ out) {
    extern __shared__ char smem[];
    const uint32_t sbase = smem_u32(smem);
    const int tid = threadIdx.x;
    const int wid = tid >> 5;
    const int lid = tid & 31;

    const int t0 = blockIdx.x * BM;   // m fastest-varying (B-tile L2 reuse)
    const int o0 = blockIdx.y * BN;

    if (tid == 0) {
        #pragma unroll
        for (int st = 0; st < NSTAGE; st++) mbar_init(sbase + SMEM_BARS + st * 8, 1);
    }
    __syncthreads();

    auto issue = [&](int kb) {
        if (kb < KBLKS && tid == 0) {
            const int st = kb % NSTAGE;
            const uint32_t mb = sbase + SMEM_BARS + st * 8;
            mbar_expect_tx(mb, STAGE_BYTES);
            const uint8_t* asrc = g_a + ((size_t)blockIdx.x * 128 + a_kblk(kb)) * A_SLAB;
            const uint8_t* bsrc = g_b + ((size_t)blockIdx.y * 128 + b_kblk(kb)) * B_SLAB;
            bulk_g2s(sbase + st * STAGE_BYTES, asrc, A_SLAB, mb);
            bulk_g2s(sbase + st * STAGE_BYTES + A_SLAB, bsrc, B_SLAB, mb);
        }
    };

    issue(0);
    issue(1);

    const int warp_m = wid & 1;
    const int warp_n = wid >> 1;           // 0..3
    const int m_off = warp_m * 64;
    const int n_off = warp_n * 64;
    const int lrow = lid & 15;
    const int lc16 = lid >> 4;

    uint32_t preA[4], preB[4];
    #pragma unroll
    for (int mi = 0; mi < 4; mi++)
        preA[mi] = swz((uint32_t)((m_off + mi * 16 + lrow) * 128 + lc16 * 16));
    #pragma unroll
    for (int nj = 0; nj < 4; nj++)
        preB[nj] = swz((uint32_t)((n_off + nj * 16 + lrow) * 128 + lc16 * 16));

    float acc[4][8][4];
    #pragma unroll
    for (int mi = 0; mi < 4; mi++)
        #pragma unroll
        for (int ni = 0; ni < 8; ni++)
            #pragma unroll
            for (int q = 0; q < 4; q++) acc[mi][ni][q] = 0.f;

    int ph[NSTAGE] = {0, 0, 0};

    for (int kb = 0; kb < KBLKS; kb++) {
        const int st = kb % NSTAGE;
        mbar_wait(sbase + SMEM_BARS + st * 8, (uint32_t)ph[st]);
        ph[st] ^= 1;
        __syncthreads();           // all warps past iter kb-1 compute -> stage reuse safe
        issue(kb + 2);             // refill stage (kb-1)%3

        const uint32_t sA = sbase + st * STAGE_BYTES;
        const uint32_t sB = sA + A_SLAB;
        #pragma unroll
        for (int ks = 0; ks < 4; ks++) {
            const uint32_t xk = ks * 32;
            uint32_t a[4][4], b[4][4];
            #pragma unroll
            for (int mi = 0; mi < 4; mi++) LDSM_X4(a[mi], sA + (preA[mi] ^ xk));
            #pragma unroll
            for (int nj = 0; nj < 4; nj++) LDSM_X4(b[nj], sB + (preB[nj] ^ xk));
            #pragma unroll
            for (int mi = 0; mi < 4; mi++)
                #pragma unroll
                for (int ni = 0; ni < 8; ni++)
                    MMA16816(acc[mi][ni], a[mi], b[ni >> 1][ni & 1], b[ni >> 1][2 + (ni & 1)]);
        }
    }

    // Epilogue: direct register -> gmem float2 stores
    #pragma unroll
    for (int mi = 0; mi < 4; mi++) {
        const int r0 = t0 + m_off + mi * 16 + (lid >> 2);
        #pragma unroll
        for (int ni = 0; ni < 8; ni++) {
            const int c = o0 + n_off + ni * 8 + ((lid & 3) << 1);
            *reinterpret_cast<float2*>(out + (size_t)r0 * O_DIM + c) =
                make_float2(acc[mi][ni][0], acc[mi][ni][1]);
            *reinterpret_cast<float2*>(out + (size_t)(r0 + 8) * O_DIM + c) =
                make_float2(acc[mi][ni][2], acc[mi][ni][3]);
        }
    }
}

// ---------------------------------------------------------------- launch
extern "C" void kernel_launch(void* const* d_in, const int* in_sizes, int n_in,
                              void* d_out, int out_size) {
    (void)in_sizes; (void)n_in; (void)out_size;
    const float* x = (const float*)d_in[0];
    const float* w = (const float*)d_in[1];
    const float* s = (const float*)d_in[2];
    float* out = (float*)d_out;

    xsplit_kernel<<<2048, 256>>>(x);
    wsplit_kernel<<<2048, 256>>>(w, s);

    cudaFuncSetAttribute(gemm_kernel, cudaFuncAttributeMaxDynamicSharedMemorySize, SMEM_TOTAL);
    dim3 grid(T_DIM / BM, O_DIM / BN);  // (64, 43), m fastest
    gemm_kernel<<<grid, NTHREADS, SMEM_TOTAL>>>(out);
}